// round 13
// baseline (speedup 1.0000x reference)
#include <cuda_runtime.h>
#include <math.h>

#define BATCH 64
#define TT 512
#define II 512
#define HH 512
#define NG 8
#define CPG 16

typedef unsigned long long ull;

__device__ __forceinline__ ull pack2(float x, float y) {
    ull r; asm("mov.b64 %0, {%1, %2};" : "=l"(r) : "f"(x), "f"(y)); return r;
}
__device__ __forceinline__ void unpack2(ull v, float& x, float& y) {
    asm("mov.b64 {%0, %1}, %2;" : "=f"(x), "=f"(y) : "l"(v));
}
__device__ __forceinline__ ull ffma2(ull a, ull b, ull c) {
    ull d; asm("fma.rn.f32x2 %0, %1, %2, %3;" : "=l"(d) : "l"(a), "l"(b), "l"(c)); return d;
}
__device__ __forceinline__ ull fadd2(ull a, ull b) {
    ull d; asm("add.rn.f32x2 %0, %1, %2;" : "=l"(d) : "l"(a), "l"(b)); return d;
}
__device__ __forceinline__ unsigned ld_acq(const unsigned* p) {
    unsigned v; asm volatile("ld.acquire.gpu.global.u32 %0, [%1];" : "=r"(v) : "l"(p) : "memory");
    return v;
}
__device__ __forceinline__ void red_rel_add1(unsigned* p) {
    asm volatile("red.release.gpu.global.add.u32 [%0], 1;" :: "l"(p) : "memory");
}
__device__ __forceinline__ float tanh_fast(float x) {
    float ax = fabsf(x);
    if (ax < 0.04f) return x * (1.0f - 0.3333333f * x * x);
    float e = __expf(2.0f * x);
    return 1.0f - __fdividef(2.0f, e + 1.0f);
}
__device__ __forceinline__ unsigned f2tf(float x) {
    unsigned r; asm("cvt.rna.tf32.f32 %0, %1;" : "=r"(r) : "f"(x)); return r;
}
__device__ __forceinline__ void mma_tf32(float* d, const unsigned* a, const unsigned* b) {
    asm volatile(
        "mma.sync.aligned.m16n8k8.row.col.f32.tf32.tf32.f32 "
        "{%0,%1,%2,%3}, {%4,%5,%6,%7}, {%8,%9}, {%0,%1,%2,%3};"
        : "+f"(d[0]), "+f"(d[1]), "+f"(d[2]), "+f"(d[3])
        : "r"(a[0]), "r"(a[1]), "r"(a[2]), "r"(a[3]), "r"(b[0]), "r"(b[1]));
}

// persistent state (R7 layout)
__device__ float    g_hT[2][HH][BATCH];
__device__ unsigned g_bar[NG * 32];

// ---------------------------------------------------------------------------
// Phase 1: 3xTF32 tensor-core GEMM, cvt done at STAGING time.
// CTA tile 128x128, BK=32, 8 warps (4Mx2N, warp 32x64), double-buffered.
// Four smem arrays: Abig/Asml [k][m], Bbig/Bsml [k][n], stride 136
// (136 mod 32 = 8 -> fragment reads hit 32 distinct banks).
// ---------------------------------------------------------------------------
#define SA 136
#define SB 136
#define ABUF (32 * SA)
#define BBUF (32 * SB)
#define GSMEM ((4 * ABUF + 4 * BBUF) * 4)

extern __shared__ unsigned gsm[];

__global__ __launch_bounds__(256, 1) void gemm_tf32_kernel(
    const float* __restrict__ X, const float* __restrict__ Wx,
    const float* __restrict__ bx, const float* __restrict__ bh,
    float* __restrict__ out)
{
    unsigned* Ab = gsm;                    // [2][ABUF]
    unsigned* As = gsm + 2 * ABUF;         // [2][ABUF]
    unsigned* Bb = gsm + 4 * ABUF;         // [2][BBUF]
    unsigned* Bs = gsm + 4 * ABUF + 2 * BBUF;

    const int tid = threadIdx.x;
    const int lane = tid & 31, wid = tid >> 5;
    const int wm = wid & 3, wn = wid >> 2;
    const int g = lane >> 2, t = lane & 3;
    const int bm = blockIdx.y * 128, bn = blockIdx.x * 128;

    float4 av[4], bv[4];
#pragma unroll
    for (int i = 0; i < 4; i++) {
        int fa = tid + i * 256;
        av[i] = *(const float4*)(X + (size_t)(bm + (fa >> 3)) * II + ((fa & 7) << 2));
        bv[i] = *(const float4*)(Wx + (size_t)(fa >> 5) * HH + bn + ((fa & 31) << 2));
    }
    // stage 0 with cvt
#pragma unroll
    for (int i = 0; i < 4; i++) {
        int fa = tid + i * 256;
        int m = fa >> 3, kq = (fa & 7) << 2;
        int kb = fa >> 5, cb = (fa & 31) << 2;
        float af[4] = { av[i].x, av[i].y, av[i].z, av[i].w };
        float bf[4] = { bv[i].x, bv[i].y, bv[i].z, bv[i].w };
#pragma unroll
        for (int j = 0; j < 4; j++) {
            unsigned big = f2tf(af[j]);
            Ab[(kq + j) * SA + m] = big;
            As[(kq + j) * SA + m] = f2tf(af[j] - __uint_as_float(big));
            unsigned bbg = f2tf(bf[j]);
            Bb[kb * SB + cb + j] = bbg;
            Bs[kb * SB + cb + j] = f2tf(bf[j] - __uint_as_float(bbg));
        }
    }
    __syncthreads();

    float acc[2][8][4];
#pragma unroll
    for (int mt = 0; mt < 2; mt++)
#pragma unroll
        for (int nt = 0; nt < 8; nt++)
#pragma unroll
            for (int q = 0; q < 4; q++) acc[mt][nt][q] = 0.0f;

    const int am = wm * 32 + g;
    const int bn0 = wn * 64 + g;

    for (int st = 0; st < 16; st++) {
        const int cur = st & 1;
        if (st < 15) {
            const int k0 = (st + 1) * 32;
#pragma unroll
            for (int i = 0; i < 4; i++) {
                int fa = tid + i * 256;
                av[i] = *(const float4*)(X + (size_t)(bm + (fa >> 3)) * II + k0 + ((fa & 7) << 2));
                bv[i] = *(const float4*)(Wx + (size_t)(k0 + (fa >> 5)) * HH + bn + ((fa & 31) << 2));
            }
        }
        const unsigned* Abc = Ab + cur * ABUF;
        const unsigned* Asc = As + cur * ABUF;
        const unsigned* Bbc = Bb + cur * BBUF;
        const unsigned* Bsc = Bs + cur * BBUF;
#pragma unroll
        for (int ks = 0; ks < 4; ks++) {
            const int kr0 = ks * 8 + t, kr1 = kr0 + 4;
            unsigned ab[2][4], asr[2][4], bb[8][2], bs[8][2];
#pragma unroll
            for (int mt = 0; mt < 2; mt++) {
                int o0 = kr0 * SA + am + mt * 16;
                int o1 = kr1 * SA + am + mt * 16;
                ab[mt][0] = Abc[o0];     ab[mt][1] = Abc[o0 + 8];
                ab[mt][2] = Abc[o1];     ab[mt][3] = Abc[o1 + 8];
                asr[mt][0] = Asc[o0];    asr[mt][1] = Asc[o0 + 8];
                asr[mt][2] = Asc[o1];    asr[mt][3] = Asc[o1 + 8];
            }
#pragma unroll
            for (int nt = 0; nt < 8; nt++) {
                int o0 = kr0 * SB + bn0 + nt * 8;
                int o1 = kr1 * SB + bn0 + nt * 8;
                bb[nt][0] = Bbc[o0];  bb[nt][1] = Bbc[o1];
                bs[nt][0] = Bsc[o0];  bs[nt][1] = Bsc[o1];
            }
#pragma unroll
            for (int mt = 0; mt < 2; mt++)
#pragma unroll
                for (int nt = 0; nt < 8; nt++) {
                    mma_tf32(acc[mt][nt], ab[mt], bb[nt]);
                    mma_tf32(acc[mt][nt], ab[mt], bs[nt]);
                    mma_tf32(acc[mt][nt], asr[mt], bb[nt]);
                }
        }
        if (st < 15) {
            const int nxt = cur ^ 1;
            __syncthreads();
#pragma unroll
            for (int i = 0; i < 4; i++) {
                int fa = tid + i * 256;
                int m = fa >> 3, kq = (fa & 7) << 2;
                int kb = fa >> 5, cb = (fa & 31) << 2;
                float af[4] = { av[i].x, av[i].y, av[i].z, av[i].w };
                float bf[4] = { bv[i].x, bv[i].y, bv[i].z, bv[i].w };
#pragma unroll
                for (int j = 0; j < 4; j++) {
                    unsigned big = f2tf(af[j]);
                    Ab[nxt * ABUF + (kq + j) * SA + m] = big;
                    As[nxt * ABUF + (kq + j) * SA + m] = f2tf(af[j] - __uint_as_float(big));
                    unsigned bbg = f2tf(bf[j]);
                    Bb[nxt * BBUF + kb * SB + cb + j] = bbg;
                    Bs[nxt * BBUF + kb * SB + cb + j] = f2tf(bf[j] - __uint_as_float(bbg));
                }
            }
            __syncthreads();
        }
    }

#pragma unroll
    for (int nt = 0; nt < 8; nt++) {
        int c = bn + wn * 64 + nt * 8 + 2 * t;
        float2 bxv = *(const float2*)&bx[c];
        float2 bhv = *(const float2*)&bh[c];
        float b0 = bxv.x + bhv.x, b1 = bxv.y + bhv.y;
#pragma unroll
        for (int mt = 0; mt < 2; mt++) {
            int r = bm + wm * 32 + mt * 16 + g;
            *(float2*)&out[(size_t)r * HH + c] =
                make_float2(acc[mt][nt][0] + b0, acc[mt][nt][1] + b1);
            *(float2*)&out[(size_t)(r + 8) * HH + c] =
                make_float2(acc[mt][nt][2] + b0, acc[mt][nt][3] + b1);
        }
    }
}

// ---------------------------------------------------------------------------
// Phase 2: recurrence — byte-identical to the round-7 best (2025us).
// ---------------------------------------------------------------------------
#define PIDX(l, w_, p_) ((l) * 33 + (w_) * 4 + (p_))

__global__ __launch_bounds__(256, 1) void rnn_kernel(
    const float* __restrict__ Wh, float* __restrict__ out)
{
    __shared__ float h_Ts[HH * 8];
    __shared__ ull   part[32 * 33];

    const int tid  = threadIdx.x;
    const int lane = tid & 31;
    const int w    = tid >> 5;
    const int jq   = lane & 15;
    const int hl   = lane >> 4;
    const int kt   = (w << 1) | hl;
    const int cg   = blockIdx.x & 15;
    const int g    = blockIdx.x >> 4;
    const int jbase = cg * 32;
    const int bbase = g * 8;

    ull w2[32][2];
#pragma unroll
    for (int i = 0; i < 32; i++) {
        float2 wv = *(const float2*)&Wh[(size_t)(kt * 32 + i) * HH + jbase + jq * 2];
        w2[i][0] = pack2(wv.x, wv.x);
        w2[i][1] = pack2(wv.y, wv.y);
    }

    const int rjc = tid & 31;
    const int rp  = (tid >> 5) & 3;
    const int rb0 = bbase + rp * 2;
    const int rj  = jbase + rjc;
    const int rlane = ((rjc & 1) << 4) | (rjc >> 1);
    const bool is_red = (tid < 128);

    float* mem = out;
    float* hid = out + (size_t)BATCH * TT * HH;
    unsigned* bar = &g_bar[g * 32];

    for (int t = 0; t < TT; t++) {
        float xw0 = 0.f, xw1 = 0.f;
        if (is_red) {
            xw0 = __ldg(&mem[((size_t)rb0 * TT + t) * HH + rj]);
            xw1 = __ldg(&mem[((size_t)(rb0 + 1) * TT + t) * HH + rj]);
        }

        ull acc[2][4];
#pragma unroll
        for (int p = 0; p < 4; p++) { acc[0][p] = 0ull; acc[1][p] = 0ull; }

        if (t > 0) {
            if (lane == 0) {
                const unsigned target = (unsigned)t * 64u;
                while (ld_acq(bar) < target) { }
            }
            __syncwarp();

            const float* gsrc = &g_hT[t & 1][0][0];
#pragma unroll
            for (int i = 0; i < 4; i++) {
                int e = tid + i * 256;
                int row = e >> 1, q = e & 1;
                float4 v = __ldcg((const float4*)&gsrc[row * BATCH + bbase + q * 4]);
                *(float4*)&h_Ts[row * 8 + q * 4] = v;
            }
            __syncthreads();

            const ulonglong2* hb = (const ulonglong2*)&h_Ts[kt * 32 * 8];
#pragma unroll
            for (int i = 0; i < 32; i++) {
                ulonglong2 u0 = hb[2 * i], u1 = hb[2 * i + 1];
                ull w0 = w2[i][0], w1 = w2[i][1];
                acc[0][0] = ffma2(u0.x, w0, acc[0][0]);
                acc[0][1] = ffma2(u0.y, w0, acc[0][1]);
                acc[0][2] = ffma2(u1.x, w0, acc[0][2]);
                acc[0][3] = ffma2(u1.y, w0, acc[0][3]);
                acc[1][0] = ffma2(u0.x, w1, acc[1][0]);
                acc[1][1] = ffma2(u0.y, w1, acc[1][1]);
                acc[1][2] = ffma2(u1.x, w1, acc[1][2]);
                acc[1][3] = ffma2(u1.y, w1, acc[1][3]);
            }
        } else {
            __syncthreads();
        }

        ull v[4];
#pragma unroll
        for (int p = 0; p < 4; p++) {
            ull give = hl ? acc[0][p] : acc[1][p];
            ull got  = __shfl_xor_sync(0xFFFFFFFFu, give, 16);
            ull keep = hl ? acc[1][p] : acc[0][p];
            v[p] = fadd2(keep, got);
        }
#pragma unroll
        for (int p = 0; p < 4; p++) part[PIDX(lane, w, p)] = v[p];
        __syncthreads();

        if (is_red) {
            ull s = part[PIDX(rlane, 0, rp)];
#pragma unroll
            for (int ww = 1; ww < 8; ww++) s = fadd2(s, part[PIDX(rlane, ww, rp)]);
            float a0, a1; unpack2(s, a0, a1);
            float r0 = tanh_fast(xw0 + a0);
            float r1 = tanh_fast(xw1 + a1);
            mem[((size_t)rb0 * TT + t) * HH + rj] = r0;
            mem[((size_t)(rb0 + 1) * TT + t) * HH + rj] = r1;
            *(float2*)&g_hT[(t + 1) & 1][rj][rb0] = make_float2(r0, r1);
            if (t == TT - 1) {
                hid[(size_t)rb0 * HH + rj] = r0;
                hid[(size_t)(rb0 + 1) * HH + rj] = r1;
            }
            if (t < TT - 1) {
                __syncwarp();
                if (lane == 0) red_rel_add1(bar);
            }
        }
    }

    __syncthreads();
    if (tid == 0) {
        red_rel_add1(bar);
        if (cg == 0) {
            const unsigned full = 511u * 64u + 16u;
            while (ld_acq(bar) < full) { }
            atomicExch(bar, 0u);
        }
    }
}

// ---------------------------------------------------------------------------
extern "C" void kernel_launch(void* const* d_in, const int* in_sizes, int n_in,
                              void* d_out, int out_size) {
    const float* x  = (const float*)d_in[0];
    const float* Wx = (const float*)d_in[1];
    const float* Wh = (const float*)d_in[2];
    const float* bx = (const float*)d_in[3];
    const float* bh = (const float*)d_in[4];
    float* out = (float*)d_out;

    cudaFuncSetAttribute(gemm_tf32_kernel,
                         cudaFuncAttributeMaxDynamicSharedMemorySize, GSMEM);

    dim3 ggrid(HH / 128, (BATCH * TT) / 128);   // (4, 256)
    gemm_tf32_kernel<<<ggrid, 256, GSMEM>>>(x, Wx, bx, bh, out);
    rnn_kernel<<<128, 256>>>(Wh, out);
}

// round 17
// speedup vs baseline: 1.3120x; 1.3120x over previous
#include <cuda_runtime.h>
#include <math.h>

#define BATCH 64
#define TT 512
#define II 512
#define HH 512
#define NG 8      // batch groups (8 batches each)
#define CPG 16    // CTAs per group (32 cols each)

typedef unsigned long long ull;

__device__ __forceinline__ ull pack2(float x, float y) {
    ull r; asm("mov.b64 %0, {%1, %2};" : "=l"(r) : "f"(x), "f"(y)); return r;
}
__device__ __forceinline__ void unpack2(ull v, float& x, float& y) {
    asm("mov.b64 {%0, %1}, %2;" : "=f"(x), "=f"(y) : "l"(v));
}
__device__ __forceinline__ ull ffma2(ull a, ull b, ull c) {
    ull d; asm("fma.rn.f32x2 %0, %1, %2, %3;" : "=l"(d) : "l"(a), "l"(b), "l"(c)); return d;
}
__device__ __forceinline__ ull fadd2(ull a, ull b) {
    ull d; asm("add.rn.f32x2 %0, %1, %2;" : "=l"(d) : "l"(a), "l"(b)); return d;
}
__device__ __forceinline__ unsigned ld_acq(const unsigned* p) {
    unsigned v; asm volatile("ld.acquire.gpu.global.u32 %0, [%1];" : "=r"(v) : "l"(p) : "memory");
    return v;
}
__device__ __forceinline__ void red_rel_add1(unsigned* p) {
    asm volatile("red.release.gpu.global.add.u32 [%0], 1;" :: "l"(p) : "memory");
}
__device__ __forceinline__ float tanh_fast(float x) {
    float ax = fabsf(x);
    if (ax < 0.04f) return x * (1.0f - 0.3333333f * x * x);
    float e = __expf(2.0f * x);
    return 1.0f - __fdividef(2.0f, e + 1.0f);
}
#define CP_ASYNC16(dst, src) \
    asm volatile("cp.async.cg.shared.global [%0], [%1], 16;" :: "r"(dst), "l"(src))
#define CP_COMMIT() asm volatile("cp.async.commit_group;" ::: "memory")
#define CP_WAIT1()  asm volatile("cp.async.wait_group 1;"  ::: "memory")

// persistent state — g_xT correctly sized this time (64MB)
__device__ float    g_hT[2][HH][BATCH];          // h transposed, ping-pong
__device__ float    g_xT[NG * TT * 4096];        // xT[g][t][i][8b]
__device__ unsigned g_bar[NG * 32];

// ---------------------------------------------------------------------------
// Transpose x: [b][t][i] -> xT[g][t][i*8 + bl]  (bl = b within group of 8)
// One CTA per (g, t): 512i x 8b tile through padded smem.
// ---------------------------------------------------------------------------
__global__ __launch_bounds__(256) void transpose_x_kernel(const float* __restrict__ X)
{
    __shared__ float s[8][520];
    const int tid = threadIdx.x;
    const int g = blockIdx.x >> 9;
    const int t = blockIdx.x & 511;

#pragma unroll
    for (int i = 0; i < 4; i++) {
        int f = tid + i * 256;              // float4 index, [0,1024)
        int bl = f >> 7, c4 = (f & 127) << 2;
        float4 v = *(const float4*)&X[((size_t)(g * 8 + bl) * TT + t) * II + c4];
        s[bl][c4 + 0] = v.x; s[bl][c4 + 1] = v.y;
        s[bl][c4 + 2] = v.z; s[bl][c4 + 3] = v.w;
    }
    __syncthreads();

    float* dst = &g_xT[((size_t)g * TT + t) * 4096];
#pragma unroll
    for (int i = 0; i < 4; i++) {
        int o = tid + i * 256;              // output float4 index, [0,1024)
        int row = o >> 1, half = o & 1;
        float4 v;
        v.x = s[half * 4 + 0][row];
        v.y = s[half * 4 + 1][row];
        v.z = s[half * 4 + 2][row];
        v.w = s[half * 4 + 3][row];
        *(float4*)&dst[(size_t)o * 4] = v;
    }
}

// ---------------------------------------------------------------------------
// Fused recurrence + input projection. 128 CTAs x 256 threads.
// CTA (g 0..7, cg 0..15): 8 batches x 32 cols. Per step:
//   1. cp.async prefetch x-tile(t+1); wait x-tile(t)
//   2. xw partial MACs (x_s, wxf pack-on-fly) into acc  <- fills idle wait
//   3. flag wait, stage h, recurrence MACs into SAME acc (R7 core)
//   4. shared fold/reduce, bias + tanh, store (R7 core)
// ---------------------------------------------------------------------------
#define PIDX(l, w_, p_) ((l) * 33 + (w_) * 4 + (p_))

extern __shared__ float rsm[];

__global__ __launch_bounds__(256, 1) void rnn_kernel(
    const float* __restrict__ Wh, const float* __restrict__ Wx,
    const float* __restrict__ bx, const float* __restrict__ bh,
    float* __restrict__ out)
{
    float* x_s  = rsm;                        // [2][4096] floats, 32KB
    float* h_Ts = rsm + 8192;                 // [512][8], 16KB
    ull*   part = (ull*)(rsm + 12288);        // [32][33], 8.4KB

    const int tid  = threadIdx.x;
    const int lane = tid & 31;
    const int w    = tid >> 5;
    const int jq   = lane & 15;
    const int hl   = lane >> 4;
    const int kt   = (w << 1) | hl;           // 0..15, i/k-chunk of 32
    const int cg   = blockIdx.x & 15;
    const int g    = blockIdx.x >> 4;
    const int jbase = cg * 32;
    const int bbase = g * 8;

    // Wh: dup-packed (critical-path loop, zero packs). Wx: plain floats
    // (64 regs), packed on the fly in the latency-filling xw loop.
    ull   w2[32][2];
    float wxf[32][2];
#pragma unroll
    for (int i = 0; i < 32; i++) {
        float2 wv = *(const float2*)&Wh[(size_t)(kt * 32 + i) * HH + jbase + jq * 2];
        w2[i][0] = pack2(wv.x, wv.x);
        w2[i][1] = pack2(wv.y, wv.y);
        float2 xv = *(const float2*)&Wx[(size_t)(kt * 32 + i) * HH + jbase + jq * 2];
        wxf[i][0] = xv.x;
        wxf[i][1] = xv.y;
    }

    // reducer mapping (tid < 128)
    const int rjc = tid & 31;
    const int rp  = (tid >> 5) & 3;
    const int rb0 = bbase + rp * 2;
    const int rj  = jbase + rjc;
    const int rlane = ((rjc & 1) << 4) | (rjc >> 1);
    const bool is_red = (tid < 128);
    float biasv = 0.f;
    if (is_red) biasv = __ldg(&bx[rj]) + __ldg(&bh[rj]);

    float* mem = out;
    float* hid = out + (size_t)BATCH * TT * HH;
    unsigned* bar = &g_bar[g * 32];

    const unsigned xs_base = (unsigned)__cvta_generic_to_shared(x_s);
    const float* xsrc = &g_xT[(size_t)g * TT * 4096];

    // prologue: prefetch x-tile for t=0 into buffer 0
#pragma unroll
    for (int i = 0; i < 4; i++) {
        int e = tid + i * 256;
        CP_ASYNC16(xs_base + e * 16, xsrc + (size_t)e * 4);
    }
    CP_COMMIT();

    for (int t = 0; t < TT; t++) {
        // prefetch x-tile(t+1)
        if (t + 1 < TT) {
            const float* src = xsrc + (size_t)(t + 1) * 4096;
            const unsigned dst0 = xs_base + ((t + 1) & 1) * 16384;
#pragma unroll
            for (int i = 0; i < 4; i++) {
                int e = tid + i * 256;
                CP_ASYNC16(dst0 + e * 16, src + (size_t)e * 4);
            }
        }
        CP_COMMIT();
        CP_WAIT1();                 // x-tile(t) complete
        __syncthreads();

        // xw partial MACs (independent of producers — fills the wait window)
        ull acc[2][4];
#pragma unroll
        for (int p = 0; p < 4; p++) { acc[0][p] = 0ull; acc[1][p] = 0ull; }
        {
            const ulonglong2* xb =
                (const ulonglong2*)&x_s[(t & 1) * 4096 + kt * 32 * 8];
#pragma unroll
            for (int i = 0; i < 32; i++) {
                ulonglong2 u0 = xb[2 * i], u1 = xb[2 * i + 1];
                ull w0 = pack2(wxf[i][0], wxf[i][0]);
                ull w1 = pack2(wxf[i][1], wxf[i][1]);
                acc[0][0] = ffma2(u0.x, w0, acc[0][0]);
                acc[0][1] = ffma2(u0.y, w0, acc[0][1]);
                acc[0][2] = ffma2(u1.x, w0, acc[0][2]);
                acc[0][3] = ffma2(u1.y, w0, acc[0][3]);
                acc[1][0] = ffma2(u0.x, w1, acc[1][0]);
                acc[1][1] = ffma2(u0.y, w1, acc[1][1]);
                acc[1][2] = ffma2(u1.x, w1, acc[1][2]);
                acc[1][3] = ffma2(u1.y, w1, acc[1][3]);
            }
        }

        if (t > 0) {
            // wait for all 16 group producers (R7-proven scheme)
            if (lane == 0) {
                const unsigned target = (unsigned)t * 64u;
                while (ld_acq(bar) < target) { }
            }
            __syncwarp();

            // stage h_t transposed
            const float* gsrc = &g_hT[t & 1][0][0];
#pragma unroll
            for (int i = 0; i < 4; i++) {
                int e = tid + i * 256;
                int row = e >> 1, q = e & 1;
                float4 v = __ldcg((const float4*)&gsrc[row * BATCH + bbase + q * 4]);
                *(float4*)&h_Ts[row * 8 + q * 4] = v;
            }
            __syncthreads();

            const ulonglong2* hb = (const ulonglong2*)&h_Ts[kt * 32 * 8];
#pragma unroll
            for (int i = 0; i < 32; i++) {
                ulonglong2 u0 = hb[2 * i], u1 = hb[2 * i + 1];
                ull w0 = w2[i][0], w1 = w2[i][1];
                acc[0][0] = ffma2(u0.x, w0, acc[0][0]);
                acc[0][1] = ffma2(u0.y, w0, acc[0][1]);
                acc[0][2] = ffma2(u1.x, w0, acc[0][2]);
                acc[0][3] = ffma2(u1.y, w0, acc[0][3]);
                acc[1][0] = ffma2(u0.x, w1, acc[1][0]);
                acc[1][1] = ffma2(u0.y, w1, acc[1][1]);
                acc[1][2] = ffma2(u1.x, w1, acc[1][2]);
                acc[1][3] = ffma2(u1.y, w1, acc[1][3]);
            }
        }

        // fold across lane bit 4
        ull v[4];
#pragma unroll
        for (int p = 0; p < 4; p++) {
            ull give = hl ? acc[0][p] : acc[1][p];
            ull got  = __shfl_xor_sync(0xFFFFFFFFu, give, 16);
            ull keep = hl ? acc[1][p] : acc[0][p];
            v[p] = fadd2(keep, got);
        }
#pragma unroll
        for (int p = 0; p < 4; p++) part[PIDX(lane, w, p)] = v[p];
        __syncthreads();

        if (is_red) {
            ull s = part[PIDX(rlane, 0, rp)];
#pragma unroll
            for (int ww = 1; ww < 8; ww++) s = fadd2(s, part[PIDX(rlane, ww, rp)]);
            float a0, a1; unpack2(s, a0, a1);
            float r0 = tanh_fast(biasv + a0);
            float r1 = tanh_fast(biasv + a1);
            mem[((size_t)rb0 * TT + t) * HH + rj] = r0;
            mem[((size_t)(rb0 + 1) * TT + t) * HH + rj] = r1;
            *(float2*)&g_hT[(t + 1) & 1][rj][rb0] = make_float2(r0, r1);
            if (t == TT - 1) {
                hid[(size_t)rb0 * HH + rj] = r0;
                hid[(size_t)(rb0 + 1) * HH + rj] = r1;
            }
            if (t < TT - 1) {
                __syncwarp();
                if (lane == 0) red_rel_add1(bar);
            }
        }
    }

    // replay reset (R7 protocol)
    __syncthreads();
    if (tid == 0) {
        red_rel_add1(bar);
        if (cg == 0) {
            const unsigned full = 511u * 64u + 16u;
            while (ld_acq(bar) < full) { }
            atomicExch(bar, 0u);
        }
    }
}

// ---------------------------------------------------------------------------
extern "C" void kernel_launch(void* const* d_in, const int* in_sizes, int n_in,
                              void* d_out, int out_size) {
    const float* x  = (const float*)d_in[0];
    const float* Wx = (const float*)d_in[1];
    const float* Wh = (const float*)d_in[2];
    const float* bx = (const float*)d_in[3];
    const float* bh = (const float*)d_in[4];
    float* out = (float*)d_out;

    const int smem = 32768 + 16384 + 32 * 33 * 8;   // 57728B
    cudaFuncSetAttribute(rnn_kernel, cudaFuncAttributeMaxDynamicSharedMemorySize, smem);

    transpose_x_kernel<<<NG * TT, 256>>>(x);
    rnn_kernel<<<128, 256, smem>>>(Wh, Wx, bx, bh, out);
}